// round 8
// baseline (speedup 1.0000x reference)
#include <cuda_runtime.h>
#include <math.h>

#define B 192
#define D 2048
#define H 128
#define LOG2PI 1.8378770664093453f
#define IG 4   // i-rows per main-kernel block

// Scratch (device globals — no allocation allowed)
__device__ __align__(16) float g_h1[B * 2 * H];
__device__ __align__(16) float g_mu[B * D];
__device__ __align__(16) float g_scale[B * D];
__device__ float g_lvpart[B * 8];

// ---------------------------------------------------------------------------
// Kernel 1: h1 = relu(q @ w1^T + b1), both heads (cols 0..127 mu, 128..255 lv).
// 4x4 register-tiled warps (lower regs -> more warps/SM than 8x4), lanes split
// K=2048. grid = (8 colgroups-of-8warps, 48 rowgroups) = 384 blocks: 2.6/SM
// for latency hiding (R7 ncu showed 8x4@192blocks was latency-bound at 15.7% occ).
// ---------------------------------------------------------------------------
__global__ void __launch_bounds__(256) gemm1_kernel(
    const float* __restrict__ q,
    const float* __restrict__ mw, const float* __restrict__ mb,
    const float* __restrict__ lw, const float* __restrict__ lb)
{
    int warp = threadIdx.x >> 5;
    int lane = threadIdx.x & 31;
    int cg   = blockIdx.x * 8 + warp;   // colgroup 0..63
    int row0 = blockIdx.y * 4;
    int col0 = cg * 4;

    const float* wbase;
    const float* bbase;
    int clocal;
    if (col0 < H) { wbase = mw; bbase = mb; clocal = col0;     }
    else          { wbase = lw; bbase = lb; clocal = col0 - H; }

    const float4* q4 = (const float4*)q;
    const float4* w4 = (const float4*)wbase;

    float acc[4][4];
    #pragma unroll
    for (int r = 0; r < 4; ++r)
        #pragma unroll
        for (int c = 0; c < 4; ++c) acc[r][c] = 0.f;

    #pragma unroll 4
    for (int it = 0; it < (D / 4) / 32; ++it) {   // 16 iters
        int k4 = lane + it * 32;
        float4 a[4], b[4];
        #pragma unroll
        for (int c = 0; c < 4; ++c) b[c] = w4[(size_t)(clocal + c) * (D / 4) + k4];
        #pragma unroll
        for (int r = 0; r < 4; ++r) a[r] = q4[(size_t)(row0 + r) * (D / 4) + k4];
        #pragma unroll
        for (int r = 0; r < 4; ++r)
            #pragma unroll
            for (int c = 0; c < 4; ++c)
                acc[r][c] += a[r].x * b[c].x + a[r].y * b[c].y
                           + a[r].z * b[c].z + a[r].w * b[c].w;
    }

    float bv[4];
    #pragma unroll
    for (int c = 0; c < 4; ++c) bv[c] = bbase[clocal + c];

    #pragma unroll
    for (int r = 0; r < 4; ++r)
        #pragma unroll
        for (int c = 0; c < 4; ++c) {
            float v = acc[r][c];
            #pragma unroll
            for (int o = 16; o; o >>= 1) v += __shfl_xor_sync(0xffffffffu, v, o);
            if (lane == 0)
                g_h1[(row0 + r) * 256 + col0 + c] = fmaxf(v + bv[c], 0.f);
        }
}

// ---------------------------------------------------------------------------
// Kernel 2 (fused layers 2+3): per block = (head, 256-col d-tile, 8 rows).
// Each block recomputes its own h2 from h1 in smem (8x redundant; ~3us
// chip-wide) and saves a kernel launch + the g_h2 global round-trip.
// ---------------------------------------------------------------------------
__global__ void __launch_bounds__(256) gemm23_kernel(
    const float* __restrict__ mw2, const float* __restrict__ mb2,
    const float* __restrict__ lw2, const float* __restrict__ lb2,
    const float* __restrict__ mw3, const float* __restrict__ mb3,
    const float* __restrict__ lw3, const float* __restrict__ lb3)
{
    __shared__ float  sh1[8][H];
    __shared__ float4 sh2[8][H / 4];
    __shared__ float  red[8][8];

    int tid  = threadIdx.x;
    int row0 = blockIdx.y * 8;
    int head = blockIdx.x >> 3;        // 0 = mu, 1 = lv

    // step 1: load h1 half-rows (8 x 128)
    #pragma unroll
    for (int i = 0; i < 4; ++i) {
        int idx = tid + i * 256;       // 0..1023
        int r = idx >> 7, k = idx & 127;
        sh1[r][k] = g_h1[(row0 + r) * 256 + head * H + k];
    }
    __syncthreads();

    // step 2: h2 = relu(h1 @ w2^T + b2). thread -> (col c, 4 rows)
    {
        const float* w2 = head ? lw2 : mw2;
        const float* b2 = head ? lb2 : mb2;
        int c    = tid & 127;
        int rgrp = tid >> 7;           // 0 or 1 -> rows rgrp*4..+3
        const float* wr = w2 + (size_t)c * H;
        float a0, a1, a2, a3;
        a0 = a1 = a2 = a3 = b2[c];
        #pragma unroll 8
        for (int k = 0; k < H; ++k) {
            float wv = wr[k];
            a0 += sh1[rgrp * 4 + 0][k] * wv;
            a1 += sh1[rgrp * 4 + 1][k] * wv;
            a2 += sh1[rgrp * 4 + 2][k] * wv;
            a3 += sh1[rgrp * 4 + 3][k] * wv;
        }
        float* sh2f = (float*)sh2;
        sh2f[(rgrp * 4 + 0) * H + c] = fmaxf(a0, 0.f);
        sh2f[(rgrp * 4 + 1) * H + c] = fmaxf(a1, 0.f);
        sh2f[(rgrp * 4 + 2) * H + c] = fmaxf(a2, 0.f);
        sh2f[(rgrp * 4 + 3) * H + c] = fmaxf(a3, 0.f);
    }
    __syncthreads();

    // step 3: layer 3 over this block's 256 d-columns
    int d = (blockIdx.x & 7) * 256 + tid;         // 0..2047 within head
    const float* wrow = (head ? lw3 : mw3) + (size_t)d * H;
    const float* bptr = head ? lb3 : mb3;

    float acc[8];
    #pragma unroll
    for (int r = 0; r < 8; ++r) acc[r] = 0.f;

    #pragma unroll
    for (int kk = 0; kk < 32; ++kk) {
        float4 w = ((const float4*)wrow)[kk];
        #pragma unroll
        for (int r = 0; r < 8; ++r) {
            float4 h = sh2[r][kk];
            acc[r] += w.x * h.x + w.y * h.y + w.z * h.z + w.w * h.w;
        }
    }
    float bias = bptr[d];

    if (!head) {
        #pragma unroll
        for (int r = 0; r < 8; ++r)
            g_mu[(size_t)(row0 + r) * D + d] = fmaxf(acc[r] + bias, 0.f);
    } else {
        int lane = tid & 31, wid = tid >> 5;
        #pragma unroll
        for (int r = 0; r < 8; ++r) {
            float v = fmaxf(acc[r] + bias, 0.f);
            g_scale[(size_t)(row0 + r) * D + d] = expf(0.25f * v);
            #pragma unroll
            for (int o = 16; o; o >>= 1) v += __shfl_xor_sync(0xffffffffu, v, o);
            if (lane == 0) red[wid][r] = v;
        }
        __syncthreads();
        if (tid == 0) {
            #pragma unroll
            for (int r = 0; r < 8; ++r) {
                float sum = 0.f;
                #pragma unroll
                for (int k = 0; k < 8; ++k) sum += red[k][r];
                g_lvpart[(row0 + r) * 8 + (blockIdx.x & 7)] = sum;
            }
        }
    }
}

// ---------------------------------------------------------------------------
// Kernel 3 (HBM-bound mainloop): R4-EXACT — block per (j, 4 i-rows), 256
// threads, 2 float4 per thread per row, mu/scale in registers, NO minBlocks
// constraint (46 regs / 5 blocks/SM is the measured local optimum; forcing 6
// blocks spilled the mu/scale registers and cost 30us in R7).
// ---------------------------------------------------------------------------
__global__ void __launch_bounds__(256) main_kernel(
    const float* __restrict__ eps,
    float* __restrict__ p,
    float* __restrict__ lp)
{
    __shared__ float red[8][IG];
    __shared__ float s_t;

    int j   = blockIdx.x % B;
    int ig  = blockIdx.x / B;
    int tid = threadIdx.x;

    const float4* m4 = (const float4*)g_mu    + (size_t)j * (D / 4);
    const float4* s4 = (const float4*)g_scale + (size_t)j * (D / 4);
    float4 m0 = m4[tid], m1 = m4[tid + 256];
    float4 s0 = s4[tid], s1 = s4[tid + 256];

    if (tid == 0) {
        float sum = 0.f;
        #pragma unroll
        for (int k = 0; k < 8; ++k) sum += g_lvpart[j * 8 + k];
        s_t = -0.25f * sum - 0.5f * (float)D * LOG2PI;
    }

    float acc[IG];
    #pragma unroll
    for (int r = 0; r < IG; ++r) {
        size_t row = (size_t)(ig * IG + r) * B + j;
        const float4* e4 = (const float4*)eps + row * (D / 4);
        float4*       p4 = (float4*)p        + row * (D / 4);

        float4 e0 = __ldcs(&e4[tid]);
        float4 e1 = __ldcs(&e4[tid + 256]);
        float4 o0, o1;
        o0.x = fmaf(e0.x, s0.x, m0.x);
        o0.y = fmaf(e0.y, s0.y, m0.y);
        o0.z = fmaf(e0.z, s0.z, m0.z);
        o0.w = fmaf(e0.w, s0.w, m0.w);
        o1.x = fmaf(e1.x, s1.x, m1.x);
        o1.y = fmaf(e1.y, s1.y, m1.y);
        o1.z = fmaf(e1.z, s1.z, m1.z);
        o1.w = fmaf(e1.w, s1.w, m1.w);
        __stcs(&p4[tid], o0);
        __stcs(&p4[tid + 256], o1);
        acc[r] = e0.x * e0.x + e0.y * e0.y + e0.z * e0.z + e0.w * e0.w
               + e1.x * e1.x + e1.y * e1.y + e1.z * e1.z + e1.w * e1.w;
    }

    int lane = tid & 31, wid = tid >> 5;
    #pragma unroll
    for (int r = 0; r < IG; ++r) {
        float v = acc[r];
        #pragma unroll
        for (int o = 16; o; o >>= 1) v += __shfl_xor_sync(0xffffffffu, v, o);
        if (lane == 0) red[wid][r] = v;
    }
    __syncthreads();
    if (tid < IG) {
        float v = 0.f;
        #pragma unroll
        for (int k = 0; k < 8; ++k) v += red[k][tid];
        lp[(size_t)(ig * IG + tid) * B + j] = -0.5f * v + s_t;
    }
}

// ---------------------------------------------------------------------------
extern "C" void kernel_launch(void* const* d_in, const int* in_sizes, int n_in,
                              void* d_out, int out_size)
{
    const float* q     = (const float*)d_in[0];
    const float* eps   = (const float*)d_in[1];
    const float* mu_w1 = (const float*)d_in[2];
    const float* mu_b1 = (const float*)d_in[3];
    const float* mu_w2 = (const float*)d_in[4];
    const float* mu_b2 = (const float*)d_in[5];
    const float* mu_w3 = (const float*)d_in[6];
    const float* mu_b3 = (const float*)d_in[7];
    const float* lv_w1 = (const float*)d_in[8];
    const float* lv_b1 = (const float*)d_in[9];
    const float* lv_w2 = (const float*)d_in[10];
    const float* lv_b2 = (const float*)d_in[11];
    const float* lv_w3 = (const float*)d_in[12];
    const float* lv_b3 = (const float*)d_in[13];

    float* p  = (float*)d_out;                       // [B, B, D]
    float* lp = (float*)d_out + (size_t)B * B * D;   // [B, B]

    gemm1_kernel<<<dim3(8, 48), 256>>>(q, mu_w1, mu_b1, lv_w1, lv_b1);
    gemm23_kernel<<<dim3(16, 24), 256>>>(mu_w2, mu_b2, lv_w2, lv_b2,
                                         mu_w3, mu_b3, lv_w3, lv_b3);
    main_kernel<<<B * (B / IG), 256>>>(eps, p, lp);
}

// round 9
// speedup vs baseline: 1.2290x; 1.2290x over previous
#include <cuda_runtime.h>
#include <math.h>

#define B 192
#define D 2048
#define H 128
#define LOG2PI 1.8378770664093453f
#define IG 4   // i-rows per main-kernel block

// Scratch (device globals — no allocation allowed)
__device__ __align__(16) float g_h1[B * 2 * H];
__device__ __align__(16) float g_h2[B * 2 * H];
__device__ __align__(16) float g_mu[B * D];
__device__ __align__(16) float g_scale[B * D];
__device__ float g_lvpart[B * 8];

// ---------------------------------------------------------------------------
// Kernel 1: h1 = relu(q @ w1^T + b1), both heads (cols 0..127 mu, 128..255 lv).
// 8x4 register-tiled warps (R4 shape: 192 blocks, measured best), with the
// block's 8 shared q rows STAGED IN SMEM (two 32KB chunks, cooperative load):
// q LDG traffic per block drops 8x and the inner loop is 4 LDG + 8 LDS per
// iter instead of 12 LDG (R7 ncu: latency-bound, DRAM 1.7%, issue 30%).
// grid = (8 colgroups-of-8warps, 24 rowgroups) x 256 threads = 192 blocks.
// ---------------------------------------------------------------------------
__global__ void __launch_bounds__(256) gemm1_kernel(
    const float* __restrict__ q,
    const float* __restrict__ mw, const float* __restrict__ mb,
    const float* __restrict__ lw, const float* __restrict__ lb)
{
    __shared__ float4 sq[8][256];       // 32 KB: 8 rows x 1024 K floats

    int tid  = threadIdx.x;
    int warp = tid >> 5;
    int lane = tid & 31;
    int cg   = blockIdx.x * 8 + warp;   // colgroup 0..63
    int row0 = blockIdx.y * 8;
    int col0 = cg * 4;

    const float* wbase;
    const float* bbase;
    int clocal;
    if (col0 < H) { wbase = mw; bbase = mb; clocal = col0;     }
    else          { wbase = lw; bbase = lb; clocal = col0 - H; }

    const float4* q4 = (const float4*)q;
    const float4* w4 = (const float4*)wbase;

    float acc[8][4];
    #pragma unroll
    for (int r = 0; r < 8; ++r)
        #pragma unroll
        for (int c = 0; c < 4; ++c) acc[r][c] = 0.f;

    #pragma unroll
    for (int kc = 0; kc < 2; ++kc) {    // two K chunks of 1024 floats
        if (kc) __syncthreads();        // protect previous chunk's reads
        // cooperative load: 8 rows x 256 f4 = 2048 f4, 8 per thread
        #pragma unroll
        for (int i = 0; i < 8; ++i) {
            int idx = tid + i * 256;    // 0..2047
            int r  = idx >> 8;
            int k4 = idx & 255;
            sq[r][k4] = q4[(size_t)(row0 + r) * (D / 4) + kc * 256 + k4];
        }
        __syncthreads();

        #pragma unroll 4
        for (int it = 0; it < 8; ++it) {
            int k4l = lane + it * 32;
            float4 b[4];
            #pragma unroll
            for (int c = 0; c < 4; ++c)
                b[c] = w4[(size_t)(clocal + c) * (D / 4) + kc * 256 + k4l];
            #pragma unroll
            for (int r = 0; r < 8; ++r) {
                float4 a = sq[r][k4l];
                #pragma unroll
                for (int c = 0; c < 4; ++c)
                    acc[r][c] += a.x * b[c].x + a.y * b[c].y
                               + a.z * b[c].z + a.w * b[c].w;
            }
        }
    }

    float bv[4];
    #pragma unroll
    for (int c = 0; c < 4; ++c) bv[c] = bbase[clocal + c];

    #pragma unroll
    for (int r = 0; r < 8; ++r)
        #pragma unroll
        for (int c = 0; c < 4; ++c) {
            float v = acc[r][c];
            #pragma unroll
            for (int o = 16; o; o >>= 1) v += __shfl_xor_sync(0xffffffffu, v, o);
            if (lane == 0)
                g_h1[(row0 + r) * 256 + col0 + c] = fmaxf(v + bv[c], 0.f);
        }
}

// ---------------------------------------------------------------------------
// Kernel 2: h2 = relu(h1 @ w2^T + b2). 8 rows per block (24 blocks). R4-exact.
// ---------------------------------------------------------------------------
__global__ void __launch_bounds__(256) gemm2_kernel(
    const float* __restrict__ mw, const float* __restrict__ mb,
    const float* __restrict__ lw, const float* __restrict__ lb)
{
    __shared__ float s[8][256];
    int row0 = blockIdx.x * 8;
    int tid = threadIdx.x;

    #pragma unroll
    for (int r = 0; r < 8; ++r)
        s[r][tid] = g_h1[(row0 + r) * 256 + tid];
    __syncthreads();

    const float* w;
    float bias;
    int hoff;
    if (tid < H) { w = mw + (size_t)tid * H;       bias = mb[tid];     hoff = 0; }
    else         { w = lw + (size_t)(tid - H) * H; bias = lb[tid - H]; hoff = H; }

    float acc[8];
    #pragma unroll
    for (int r = 0; r < 8; ++r) acc[r] = bias;

    #pragma unroll 8
    for (int k = 0; k < H; ++k) {
        float wv = w[k];
        #pragma unroll
        for (int r = 0; r < 8; ++r) acc[r] += s[r][hoff + k] * wv;
    }
    #pragma unroll
    for (int r = 0; r < 8; ++r)
        g_h2[(row0 + r) * 256 + tid] = fmaxf(acc[r], 0.f);
}

// ---------------------------------------------------------------------------
// Kernel 3: layer-3 for both heads, 8 rows per block, h2 half-rows in smem.
// R4-exact.
// ---------------------------------------------------------------------------
__global__ void __launch_bounds__(256) gemm3_kernel(
    const float* __restrict__ mw, const float* __restrict__ mb,
    const float* __restrict__ lw, const float* __restrict__ lb)
{
    __shared__ float4 s4[8][32];
    __shared__ float red[8][8];

    int tid  = threadIdx.x;
    int row0 = blockIdx.y * 8;
    int head = blockIdx.x >> 3;        // 0 = mu, 1 = lv

    {
        int r  = tid >> 5;
        int kk = tid & 31;
        s4[r][kk] = ((const float4*)(g_h2 + (row0 + r) * 256 + head * H))[kk];
    }
    __syncthreads();

    int d = (blockIdx.x & 7) * 256 + tid;
    const float* wrow = (head ? lw : mw) + (size_t)d * H;
    const float* bptr = head ? lb : mb;

    float acc[8];
    #pragma unroll
    for (int r = 0; r < 8; ++r) acc[r] = 0.f;

    #pragma unroll
    for (int kk = 0; kk < 32; ++kk) {
        float4 w = ((const float4*)wrow)[kk];
        #pragma unroll
        for (int r = 0; r < 8; ++r) {
            float4 h = s4[r][kk];
            acc[r] += w.x * h.x + w.y * h.y + w.z * h.z + w.w * h.w;
        }
    }
    float bias = bptr[d];

    if (!head) {
        #pragma unroll
        for (int r = 0; r < 8; ++r)
            g_mu[(size_t)(row0 + r) * D + d] = fmaxf(acc[r] + bias, 0.f);
    } else {
        int lane = tid & 31, wid = tid >> 5;
        #pragma unroll
        for (int r = 0; r < 8; ++r) {
            float v = fmaxf(acc[r] + bias, 0.f);
            g_scale[(size_t)(row0 + r) * D + d] = expf(0.25f * v);
            #pragma unroll
            for (int o = 16; o; o >>= 1) v += __shfl_xor_sync(0xffffffffu, v, o);
            if (lane == 0) red[wid][r] = v;
        }
        __syncthreads();
        if (tid == 0) {
            #pragma unroll
            for (int r = 0; r < 8; ++r) {
                float sum = 0.f;
                #pragma unroll
                for (int k = 0; k < 8; ++k) sum += red[k][r];
                g_lvpart[(row0 + r) * 8 + (blockIdx.x & 7)] = sum;
            }
        }
    }
}

// ---------------------------------------------------------------------------
// Kernel 4 (HBM-bound mainloop): R4-EXACT — block per (j, 4 i-rows), 256
// threads, 2 float4 per thread per row, mu/scale in registers, NO minBlocks
// constraint (46 regs / 5 blocks/SM is the measured optimum; forcing 6 spilled).
// ---------------------------------------------------------------------------
__global__ void __launch_bounds__(256) main_kernel(
    const float* __restrict__ eps,
    float* __restrict__ p,
    float* __restrict__ lp)
{
    __shared__ float red[8][IG];
    __shared__ float s_t;

    int j   = blockIdx.x % B;
    int ig  = blockIdx.x / B;
    int tid = threadIdx.x;

    const float4* m4 = (const float4*)g_mu    + (size_t)j * (D / 4);
    const float4* s4 = (const float4*)g_scale + (size_t)j * (D / 4);
    float4 m0 = m4[tid], m1 = m4[tid + 256];
    float4 s0 = s4[tid], s1 = s4[tid + 256];

    if (tid == 0) {
        float sum = 0.f;
        #pragma unroll
        for (int k = 0; k < 8; ++k) sum += g_lvpart[j * 8 + k];
        s_t = -0.25f * sum - 0.5f * (float)D * LOG2PI;
    }

    float acc[IG];
    #pragma unroll
    for (int r = 0; r < IG; ++r) {
        size_t row = (size_t)(ig * IG + r) * B + j;
        const float4* e4 = (const float4*)eps + row * (D / 4);
        float4*       p4 = (float4*)p        + row * (D / 4);

        float4 e0 = __ldcs(&e4[tid]);
        float4 e1 = __ldcs(&e4[tid + 256]);
        float4 o0, o1;
        o0.x = fmaf(e0.x, s0.x, m0.x);
        o0.y = fmaf(e0.y, s0.y, m0.y);
        o0.z = fmaf(e0.z, s0.z, m0.z);
        o0.w = fmaf(e0.w, s0.w, m0.w);
        o1.x = fmaf(e1.x, s1.x, m1.x);
        o1.y = fmaf(e1.y, s1.y, m1.y);
        o1.z = fmaf(e1.z, s1.z, m1.z);
        o1.w = fmaf(e1.w, s1.w, m1.w);
        __stcs(&p4[tid], o0);
        __stcs(&p4[tid + 256], o1);
        acc[r] = e0.x * e0.x + e0.y * e0.y + e0.z * e0.z + e0.w * e0.w
               + e1.x * e1.x + e1.y * e1.y + e1.z * e1.z + e1.w * e1.w;
    }

    int lane = tid & 31, wid = tid >> 5;
    #pragma unroll
    for (int r = 0; r < IG; ++r) {
        float v = acc[r];
        #pragma unroll
        for (int o = 16; o; o >>= 1) v += __shfl_xor_sync(0xffffffffu, v, o);
        if (lane == 0) red[wid][r] = v;
    }
    __syncthreads();
    if (tid < IG) {
        float v = 0.f;
        #pragma unroll
        for (int k = 0; k < 8; ++k) v += red[k][tid];
        lp[(size_t)(ig * IG + tid) * B + j] = -0.5f * v + s_t;
    }
}

// ---------------------------------------------------------------------------
extern "C" void kernel_launch(void* const* d_in, const int* in_sizes, int n_in,
                              void* d_out, int out_size)
{
    const float* q     = (const float*)d_in[0];
    const float* eps   = (const float*)d_in[1];
    const float* mu_w1 = (const float*)d_in[2];
    const float* mu_b1 = (const float*)d_in[3];
    const float* mu_w2 = (const float*)d_in[4];
    const float* mu_b2 = (const float*)d_in[5];
    const float* mu_w3 = (const float*)d_in[6];
    const float* mu_b3 = (const float*)d_in[7];
    const float* lv_w1 = (const float*)d_in[8];
    const float* lv_b1 = (const float*)d_in[9];
    const float* lv_w2 = (const float*)d_in[10];
    const float* lv_b2 = (const float*)d_in[11];
    const float* lv_w3 = (const float*)d_in[12];
    const float* lv_b3 = (const float*)d_in[13];

    float* p  = (float*)d_out;                       // [B, B, D]
    float* lp = (float*)d_out + (size_t)B * B * D;   // [B, B]

    gemm1_kernel<<<dim3(8, 24), 256>>>(q, mu_w1, mu_b1, lv_w1, lv_b1);
    gemm2_kernel<<<B / 8, 256>>>(mu_w2, mu_b2, lv_w2, lv_b2);
    gemm3_kernel<<<dim3(16, 24), 256>>>(mu_w3, mu_b3, lv_w3, lv_b3);
    main_kernel<<<B * (B / IG), 256>>>(eps, p, lp);
}

// round 10
// speedup vs baseline: 1.2606x; 1.0257x over previous
#include <cuda_runtime.h>
#include <math.h>

#define B 192
#define D 2048
#define H 128
#define LOG2PI 1.8378770664093453f
#define IG 4   // i-rows per main-kernel block

// Scratch (device globals — no allocation allowed)
__device__ __align__(16) float g_h1[B * 2 * H];
__device__ __align__(16) float g_h2[B * 2 * H];
__device__ __align__(16) float g_mu[B * D];
__device__ __align__(16) float g_scale[B * D];
__device__ float g_lvpart[B * 8];

// ---------------------------------------------------------------------------
// Kernel 1 (R4-exact): h1 = relu(q @ w1^T + b1), both heads.
// 8x4 register-tiled warps, lanes split K=2048.
// grid = (8 colgroups-of-8warps, 24 rowgroups) x 256 threads = 192 blocks.
// ---------------------------------------------------------------------------
__global__ void __launch_bounds__(256) gemm1_kernel(
    const float* __restrict__ q,
    const float* __restrict__ mw, const float* __restrict__ mb,
    const float* __restrict__ lw, const float* __restrict__ lb)
{
    int warp = threadIdx.x >> 5;
    int lane = threadIdx.x & 31;
    int cg   = blockIdx.x * 8 + warp;   // colgroup 0..63
    int row0 = blockIdx.y * 8;
    int col0 = cg * 4;

    const float* wbase;
    const float* bbase;
    int clocal;
    if (col0 < H) { wbase = mw; bbase = mb; clocal = col0;     }
    else          { wbase = lw; bbase = lb; clocal = col0 - H; }

    const float4* q4 = (const float4*)q;
    const float4* w4 = (const float4*)wbase;

    float acc[8][4];
    #pragma unroll
    for (int r = 0; r < 8; ++r)
        #pragma unroll
        for (int c = 0; c < 4; ++c) acc[r][c] = 0.f;

    #pragma unroll 4
    for (int it = 0; it < (D / 4) / 32; ++it) {   // 16 iters
        int k4 = lane + it * 32;
        float4 b[4];
        #pragma unroll
        for (int c = 0; c < 4; ++c) b[c] = w4[(size_t)(clocal + c) * (D / 4) + k4];
        #pragma unroll
        for (int r = 0; r < 8; ++r) {
            float4 a = q4[(size_t)(row0 + r) * (D / 4) + k4];
            #pragma unroll
            for (int c = 0; c < 4; ++c)
                acc[r][c] += a.x * b[c].x + a.y * b[c].y
                           + a.z * b[c].z + a.w * b[c].w;
        }
    }

    float bv[4];
    #pragma unroll
    for (int c = 0; c < 4; ++c) bv[c] = bbase[clocal + c];

    #pragma unroll
    for (int r = 0; r < 8; ++r)
        #pragma unroll
        for (int c = 0; c < 4; ++c) {
            float v = acc[r][c];
            #pragma unroll
            for (int o = 16; o; o >>= 1) v += __shfl_xor_sync(0xffffffffu, v, o);
            if (lane == 0)
                g_h1[(row0 + r) * 256 + col0 + c] = fmaxf(v + bv[c], 0.f);
        }
}

// ---------------------------------------------------------------------------
// Kernel 2 (R4-exact): h2 = relu(h1 @ w2^T + b2). 8 rows per block.
// ---------------------------------------------------------------------------
__global__ void __launch_bounds__(256) gemm2_kernel(
    const float* __restrict__ mw, const float* __restrict__ mb,
    const float* __restrict__ lw, const float* __restrict__ lb)
{
    __shared__ float s[8][256];
    int row0 = blockIdx.x * 8;
    int tid = threadIdx.x;

    #pragma unroll
    for (int r = 0; r < 8; ++r)
        s[r][tid] = g_h1[(row0 + r) * 256 + tid];
    __syncthreads();

    const float* w;
    float bias;
    int hoff;
    if (tid < H) { w = mw + (size_t)tid * H;       bias = mb[tid];     hoff = 0; }
    else         { w = lw + (size_t)(tid - H) * H; bias = lb[tid - H]; hoff = H; }

    float acc[8];
    #pragma unroll
    for (int r = 0; r < 8; ++r) acc[r] = bias;

    #pragma unroll 8
    for (int k = 0; k < H; ++k) {
        float wv = w[k];
        #pragma unroll
        for (int r = 0; r < 8; ++r) acc[r] += s[r][hoff + k] * wv;
    }
    #pragma unroll
    for (int r = 0; r < 8; ++r)
        g_h2[(row0 + r) * 256 + tid] = fmaxf(acc[r], 0.f);
}

// ---------------------------------------------------------------------------
// Kernel 3 (R4-exact): layer-3 for both heads, 8 rows per block.
// ---------------------------------------------------------------------------
__global__ void __launch_bounds__(256) gemm3_kernel(
    const float* __restrict__ mw, const float* __restrict__ mb,
    const float* __restrict__ lw, const float* __restrict__ lb)
{
    __shared__ float4 s4[8][32];
    __shared__ float red[8][8];

    int tid  = threadIdx.x;
    int row0 = blockIdx.y * 8;
    int head = blockIdx.x >> 3;        // 0 = mu, 1 = lv

    {
        int r  = tid >> 5;
        int kk = tid & 31;
        s4[r][kk] = ((const float4*)(g_h2 + (row0 + r) * 256 + head * H))[kk];
    }
    __syncthreads();

    int d = (blockIdx.x & 7) * 256 + tid;
    const float* wrow = (head ? lw : mw) + (size_t)d * H;
    const float* bptr = head ? lb : mb;

    float acc[8];
    #pragma unroll
    for (int r = 0; r < 8; ++r) acc[r] = 0.f;

    #pragma unroll
    for (int kk = 0; kk < 32; ++kk) {
        float4 w = ((const float4*)wrow)[kk];
        #pragma unroll
        for (int r = 0; r < 8; ++r) {
            float4 h = s4[r][kk];
            acc[r] += w.x * h.x + w.y * h.y + w.z * h.z + w.w * h.w;
        }
    }
    float bias = bptr[d];

    if (!head) {
        #pragma unroll
        for (int r = 0; r < 8; ++r)
            g_mu[(size_t)(row0 + r) * D + d] = fmaxf(acc[r] + bias, 0.f);
    } else {
        int lane = tid & 31, wid = tid >> 5;
        #pragma unroll
        for (int r = 0; r < 8; ++r) {
            float v = fmaxf(acc[r] + bias, 0.f);
            g_scale[(size_t)(row0 + r) * D + d] = expf(0.25f * v);
            #pragma unroll
            for (int o = 16; o; o >>= 1) v += __shfl_xor_sync(0xffffffffu, v, o);
            if (lane == 0) red[wid][r] = v;
        }
        __syncthreads();
        if (tid == 0) {
            #pragma unroll
            for (int r = 0; r < 8; ++r) {
                float sum = 0.f;
                #pragma unroll
                for (int k = 0; k < 8; ++k) sum += red[k][r];
                g_lvpart[(row0 + r) * 8 + (blockIdx.x & 7)] = sum;
            }
        }
    }
}

// ---------------------------------------------------------------------------
// Kernel 4 (HBM-bound mainloop): block per (j, 4 i-rows), 256 threads,
// mu/scale in registers. CHANGE vs R4: rows processed in PAIRS with all 4
// eps float4 loads issued back-to-back before any consumption -> per-thread
// MLP 2 -> 4 (R9 ncu: issue 12.9%, DRAM 80.6% = latency-limited).
// ---------------------------------------------------------------------------
__global__ void __launch_bounds__(256) main_kernel(
    const float* __restrict__ eps,
    float* __restrict__ p,
    float* __restrict__ lp)
{
    __shared__ float red[8][IG];
    __shared__ float s_t;

    int j   = blockIdx.x % B;
    int ig  = blockIdx.x / B;
    int tid = threadIdx.x;

    const float4* m4 = (const float4*)g_mu    + (size_t)j * (D / 4);
    const float4* s4 = (const float4*)g_scale + (size_t)j * (D / 4);
    float4 m0 = m4[tid], m1 = m4[tid + 256];
    float4 s0 = s4[tid], s1 = s4[tid + 256];

    if (tid == 0) {
        float sum = 0.f;
        #pragma unroll
        for (int k = 0; k < 8; ++k) sum += g_lvpart[j * 8 + k];
        s_t = -0.25f * sum - 0.5f * (float)D * LOG2PI;
    }

    float acc[IG];
    #pragma unroll
    for (int rp = 0; rp < IG / 2; ++rp) {        // row pairs
        int ra = rp * 2, rb = rp * 2 + 1;
        size_t rowa = (size_t)(ig * IG + ra) * B + j;
        size_t rowb = (size_t)(ig * IG + rb) * B + j;
        const float4* ea4 = (const float4*)eps + rowa * (D / 4);
        const float4* eb4 = (const float4*)eps + rowb * (D / 4);
        float4*       pa4 = (float4*)p        + rowa * (D / 4);
        float4*       pb4 = (float4*)p        + rowb * (D / 4);

        // 4 independent loads in flight before any use
        float4 ea0 = __ldcs(&ea4[tid]);
        float4 ea1 = __ldcs(&ea4[tid + 256]);
        float4 eb0 = __ldcs(&eb4[tid]);
        float4 eb1 = __ldcs(&eb4[tid + 256]);

        float4 o;
        o.x = fmaf(ea0.x, s0.x, m0.x);
        o.y = fmaf(ea0.y, s0.y, m0.y);
        o.z = fmaf(ea0.z, s0.z, m0.z);
        o.w = fmaf(ea0.w, s0.w, m0.w);
        __stcs(&pa4[tid], o);
        o.x = fmaf(ea1.x, s1.x, m1.x);
        o.y = fmaf(ea1.y, s1.y, m1.y);
        o.z = fmaf(ea1.z, s1.z, m1.z);
        o.w = fmaf(ea1.w, s1.w, m1.w);
        __stcs(&pa4[tid + 256], o);
        o.x = fmaf(eb0.x, s0.x, m0.x);
        o.y = fmaf(eb0.y, s0.y, m0.y);
        o.z = fmaf(eb0.z, s0.z, m0.z);
        o.w = fmaf(eb0.w, s0.w, m0.w);
        __stcs(&pb4[tid], o);
        o.x = fmaf(eb1.x, s1.x, m1.x);
        o.y = fmaf(eb1.y, s1.y, m1.y);
        o.z = fmaf(eb1.z, s1.z, m1.z);
        o.w = fmaf(eb1.w, s1.w, m1.w);
        __stcs(&pb4[tid + 256], o);

        acc[ra] = ea0.x * ea0.x + ea0.y * ea0.y + ea0.z * ea0.z + ea0.w * ea0.w
                + ea1.x * ea1.x + ea1.y * ea1.y + ea1.z * ea1.z + ea1.w * ea1.w;
        acc[rb] = eb0.x * eb0.x + eb0.y * eb0.y + eb0.z * eb0.z + eb0.w * eb0.w
                + eb1.x * eb1.x + eb1.y * eb1.y + eb1.z * eb1.z + eb1.w * eb1.w;
    }

    int lane = tid & 31, wid = tid >> 5;
    #pragma unroll
    for (int r = 0; r < IG; ++r) {
        float v = acc[r];
        #pragma unroll
        for (int o = 16; o; o >>= 1) v += __shfl_xor_sync(0xffffffffu, v, o);
        if (lane == 0) red[wid][r] = v;
    }
    __syncthreads();
    if (tid < IG) {
        float v = 0.f;
        #pragma unroll
        for (int k = 0; k < 8; ++k) v += red[k][tid];
        lp[(size_t)(ig * IG + tid) * B + j] = -0.5f * v + s_t;
    }
}

// ---------------------------------------------------------------------------
extern "C" void kernel_launch(void* const* d_in, const int* in_sizes, int n_in,
                              void* d_out, int out_size)
{
    const float* q     = (const float*)d_in[0];
    const float* eps   = (const float*)d_in[1];
    const float* mu_w1 = (const float*)d_in[2];
    const float* mu_b1 = (const float*)d_in[3];
    const float* mu_w2 = (const float*)d_in[4];
    const float* mu_b2 = (const float*)d_in[5];
    const float* mu_w3 = (const float*)d_in[6];
    const float* mu_b3 = (const float*)d_in[7];
    const float* lv_w1 = (const float*)d_in[8];
    const float* lv_b1 = (const float*)d_in[9];
    const float* lv_w2 = (const float*)d_in[10];
    const float* lv_b2 = (const float*)d_in[11];
    const float* lv_w3 = (const float*)d_in[12];
    const float* lv_b3 = (const float*)d_in[13];

    float* p  = (float*)d_out;                       // [B, B, D]
    float* lp = (float*)d_out + (size_t)B * B * D;   // [B, B]

    gemm1_kernel<<<dim3(8, 24), 256>>>(q, mu_w1, mu_b1, lv_w1, lv_b1);
    gemm2_kernel<<<B / 8, 256>>>(mu_w2, mu_b2, lv_w2, lv_b2);
    gemm3_kernel<<<dim3(16, 24), 256>>>(mu_w3, mu_b3, lv_w3, lv_b3);
    main_kernel<<<B * (B / IG), 256>>>(eps, p, lp);
}